// round 16
// baseline (speedup 1.0000x reference)
#include <cuda_runtime.h>
#include <math.h>

// Problem constants
#define BB 2
#define SS 4096
#define EE 512
#define HH 8
#define DD 64
#define WW 512
#define NWIN 8            // SS / WW
#define NBUCKETS 32
#define UU (WW + SS)      // unified key axis: [0,W) prev, [W, W+S) current

#define NEGINF (-INFINITY)
#define SMAX 16.0f        // static softmax shift (scores are O(+-10))

// Scratch fp32 (k,v needed by tail kernel; v by vt_pack)
__device__ float g_k[BB*HH*SS*DD];
__device__ float g_v[BB*HH*SS*DD];

// bf16x2-packed hi/lo splits for the proj GEMM, pair-permuted per 16-pair chunk
__device__ __align__(16) unsigned g_xp_hi[BB*SS*EE/2];     // [m][256]
__device__ __align__(16) unsigned g_xp_lo[BB*SS*EE/2];
__device__ __align__(16) unsigned g_wp_hi[3*EE*HH*DD/2];   // [zb][n][256] (transposed)
__device__ __align__(16) unsigned g_wp_lo[3*EE*HH*DD/2];

// Packed attention operands (bf16x2 hi/lo)
__device__ __align__(16) unsigned g_Qh[BB*HH*SS*32];       // [b][h][s][pos]
__device__ __align__(16) unsigned g_Ql[BB*HH*SS*32];
__device__ __align__(16) unsigned g_Kh[BB*HH*UU*32];       // [b][h][u][pos]
__device__ __align__(16) unsigned g_Kl[BB*HH*UU*32];
__device__ __align__(16) unsigned g_Vh[BB*HH*DD*(UU/2)];   // [b][h][d][sp]
__device__ __align__(16) unsigned g_Vl[BB*HH*DD*(UU/2)];

// ---------------------------------------------------------------------------
// helpers
// ---------------------------------------------------------------------------
__device__ __forceinline__ void mma_bf16(float c[4], const unsigned a[4],
                                         unsigned b0, unsigned b1) {
    asm volatile(
        "mma.sync.aligned.m16n8k16.row.col.f32.bf16.bf16.f32 "
        "{%0,%1,%2,%3}, {%4,%5,%6,%7}, {%8,%9}, {%0,%1,%2,%3};"
        : "+f"(c[0]), "+f"(c[1]), "+f"(c[2]), "+f"(c[3])
        : "r"(a[0]), "r"(a[1]), "r"(a[2]), "r"(a[3]), "r"(b0), "r"(b1));
}

// pack two f32 into bf16x2: lower half = first arg, upper half = second arg
__device__ __forceinline__ unsigned packbf(float lo, float hi) {
    unsigned r;
    asm("cvt.rn.bf16x2.f32 %0, %1, %2;" : "=r"(r) : "f"(hi), "f"(lo));
    return r;
}

__device__ __forceinline__ void cp16(unsigned s, const void* g) {
    asm volatile("cp.async.cg.shared.global [%0], [%1], 16;" :: "r"(s), "l"(g));
}
__device__ __forceinline__ void cp_commit() { asm volatile("cp.async.commit_group;"); }
__device__ __forceinline__ void cp_wait1()  { asm volatile("cp.async.wait_group 1;"); }
__device__ __forceinline__ void cp_wait0()  { asm volatile("cp.async.wait_group 0;"); }

// ---------------------------------------------------------------------------
// Pre-split xs (proj A operand): packed bf16x2 hi/lo, pair-permuted
// ---------------------------------------------------------------------------
__global__ __launch_bounds__(256) void split_xs_kernel(const float* __restrict__ xs)
{
    int id = blockIdx.x * 256 + threadIdx.x;       // < B*S*E/2 = 2M
    int m  = id >> 8;
    int pk = id & 255;
    float x0 = xs[m * 512 + 2 * pk];
    float x1 = xs[m * 512 + 2 * pk + 1];
    unsigned ph = packbf(x0, x1);
    float f0 = __uint_as_float(ph << 16);
    float f1 = __uint_as_float(ph & 0xFFFF0000u);
    unsigned pl = packbf(x0 - f0, x1 - f1);
    int j  = pk & 15, ch = pk >> 4;
    int pos = (m << 8) | (ch << 4) | ((j & 3) << 2) | (j >> 2);
    g_xp_hi[pos] = ph;
    g_xp_lo[pos] = pl;
}

// ---------------------------------------------------------------------------
// Pre-split weights: transpose [e][n] -> [n][e], pack bf16x2 hi/lo, permute.
// ---------------------------------------------------------------------------
__global__ __launch_bounds__(256) void split_w_kernel(
    const float* __restrict__ wq,
    const float* __restrict__ wk,
    const float* __restrict__ wv)
{
    const int zb = blockIdx.z;
    const float* w = (zb == 0) ? wq : (zb == 1) ? wk : wv;

    __shared__ float t[32][33];

    const int e0 = blockIdx.x * 32;
    const int n0 = blockIdx.y * 32;
    const int lx = threadIdx.x & 31;
    const int ly = threadIdx.x >> 5;

    #pragma unroll
    for (int r = 0; r < 4; r++) {
        int e = e0 + ly + r * 8;
        t[lx][ly + r * 8] = w[e * 512 + n0 + lx];
    }
    __syncthreads();

    for (int i = threadIdx.x; i < 32 * 16; i += 256) {
        int n_local = i >> 4;
        int j = i & 15;
        float x0 = t[n_local][2 * j];
        float x1 = t[n_local][2 * j + 1];
        unsigned ph = packbf(x0, x1);
        float f0 = __uint_as_float(ph << 16);
        float f1 = __uint_as_float(ph & 0xFFFF0000u);
        unsigned pl = packbf(x0 - f0, x1 - f1);
        int pos = (zb * 512 + n0 + n_local) * 256 + (blockIdx.x << 4)
                  + ((j & 3) << 2) + (j >> 2);
        g_wp_hi[pos] = ph;
        g_wp_lo[pos] = pl;
    }
}

// ---------------------------------------------------------------------------
// Pack prev_k into unified K rows [0, W)
// ---------------------------------------------------------------------------
__global__ __launch_bounds__(256) void pk_pack_kernel(const float* __restrict__ prev_k)
{
    int id = blockIdx.x * 256 + threadIdx.x;       // < B*W*H*32 = 262144
    int dp = id & 31;
    int h  = (id >> 5) & 7;
    int w  = (id >> 8) & 511;
    int b  = id >> 17;
    const float* src = prev_k + (((size_t)(b * WW + w) * HH + h) * DD) + 2 * dp;
    float x0 = src[0], x1 = src[1];
    unsigned ph = packbf(x0, x1);
    float f0 = __uint_as_float(ph << 16);
    float f1 = __uint_as_float(ph & 0xFFFF0000u);
    int pos = ((dp & 7) << 2) | (dp >> 3);
    size_t dst = ((size_t)(b * HH + h) * UU + w) * 32 + pos;
    g_Kh[dst] = ph;
    g_Kl[dst] = packbf(x0 - f0, x1 - f1);
}

// ---------------------------------------------------------------------------
// V transpose + pack: g_Vh/g_Vl [b][h][d][sp], sp = unified s-pair.
// grid (36, B*H), block 256.  Chunk = 128 unified rows.
// ---------------------------------------------------------------------------
__global__ __launch_bounds__(256) void vt_pack_kernel(const float* __restrict__ prev_v)
{
    __shared__ float tile[128][65];
    const int c  = blockIdx.x;                     // 0..35
    const int bh = blockIdx.y;                     // 0..15
    const int b = bh >> 3, h = bh & 7;
    const int t = threadIdx.x;

    for (int i = t; i < 128 * 64; i += 256) {
        int row = i >> 6, d = i & 63;
        int u = c * 128 + row;
        float val;
        if (u < WW)
            val = prev_v[(((size_t)(b * WW + u) * HH + h) * DD) + d];
        else
            val = g_v[(((size_t)(b * HH + h) * SS + (u - WW)) * DD) + d];
        tile[row][d] = val;
    }
    __syncthreads();

    for (int i = t; i < 64 * 64; i += 256) {
        int d = i >> 6, spl = i & 63;
        float x0 = tile[2 * spl][d];
        float x1 = tile[2 * spl + 1][d];
        unsigned ph = packbf(x0, x1);
        float f0 = __uint_as_float(ph << 16);
        float f1 = __uint_as_float(ph & 0xFFFF0000u);
        size_t dst = ((size_t)(b * HH + h) * DD + d) * (UU / 2) + c * 64 + spl;
        g_Vh[dst] = ph;
        g_Vl[dst] = packbf(x0 - f0, x1 - f1);
    }
}

// ---------------------------------------------------------------------------
// Projection via bf16-split (3-term) m16n8k16 GEMM.
// 512 threads, 16 warps (4x4 grid of 32x32 warp tiles).
// K-chunks of 64 (two 32-k sub-chunks per barrier section) -> 8 chunk
// iterations, 16 barriers total.  Double-buffered smem, stride-36 rows:
// 2 buf x 4 arrays x 128x36 words = 147456 B.
// Epilogue: zb=0 -> packed Q; zb=1 -> fp32 K + packed K; zb=2 -> fp32 V.
// ---------------------------------------------------------------------------
#define PROJ_ARR  4608                 // words per array (128*36)
#define PROJ_BUF  (4 * PROJ_ARR)       // words per buffer
#define PROJ_SMEM (2 * PROJ_BUF * 4)   // 147456 bytes

__global__ __launch_bounds__(512, 1) void proj_kernel()
{
    extern __shared__ unsigned smem[];

    const int zb = blockIdx.z;
    const float scale = (zb == 0) ? 0.125f : 1.0f;

    const int m0 = blockIdx.x * 128;
    const int n0 = blockIdx.y * 128;
    const int tid  = threadIdx.x;
    const int wid  = tid >> 5;
    const int lane = tid & 31;
    const int g    = lane >> 2;
    const int tg   = lane & 3;
    const int wm   = wid >> 2;      // 0..3 (32 rows each)
    const int wn   = wid & 3;       // 0..3 (32 cols each)

    unsigned smem_u32;
    {
        void* p = smem;
        asm("{ .reg .u64 t; cvta.to.shared.u64 t, %1; cvt.u32.u64 %0, t; }"
            : "=r"(smem_u32) : "l"(p));
    }

    float acc[2][4][4];
    #pragma unroll
    for (int mt = 0; mt < 2; mt++)
        #pragma unroll
        for (int nt = 0; nt < 4; nt++)
            #pragma unroll
            for (int r = 0; r < 4; r++) acc[mt][nt][r] = 0.0f;

    // stage one 64-k chunk: per array 128 rows x 32 words; 1024 cp16 / array.
    auto stage = [&](int buf, int ch) {
        unsigned base = smem_u32 + (unsigned)buf * PROJ_BUF * 4;
        #pragma unroll
        for (int r = 0; r < 2; r++) {
            int i = tid + r * 512;             // 0..1023
            int row = i >> 3, c4 = i & 7;
            unsigned d = base + (unsigned)(row * 36 + c4 * 4) * 4;
            const unsigned* aH = g_xp_hi + ((m0 + row) * 256 + ch * 32 + c4 * 4);
            const unsigned* aL = g_xp_lo + ((m0 + row) * 256 + ch * 32 + c4 * 4);
            cp16(d,                aH);
            cp16(d + PROJ_ARR * 4, aL);
            const unsigned* bH = g_wp_hi + ((size_t)(zb * 512 + n0 + row) * 256 + ch * 32 + c4 * 4);
            const unsigned* bL = g_wp_lo + ((size_t)(zb * 512 + n0 + row) * 256 + ch * 32 + c4 * 4);
            cp16(d + 2 * PROJ_ARR * 4, bH);
            cp16(d + 3 * PROJ_ARR * 4, bL);
        }
    };

    stage(0, 0);
    cp_commit();

    for (int c = 0; c < 8; c++) {
        if (c < 7) {
            stage((c + 1) & 1, c + 1);
            cp_commit();
            cp_wait1();
        } else {
            cp_wait0();
        }
        __syncthreads();

        const unsigned* Ah = smem + (c & 1) * PROJ_BUF;
        const unsigned* Al = Ah + PROJ_ARR;
        const unsigned* Bh = Ah + 2 * PROJ_ARR;
        const unsigned* Bl = Ah + 3 * PROJ_ARR;

        #pragma unroll
        for (int sub = 0; sub < 2; sub++) {
            uint4 agH[2], ahH[2], agL[2], ahL[2], bgH[4], bgL[4];
            #pragma unroll
            for (int mt = 0; mt < 2; mt++) {
                int r0 = (wm * 32 + mt * 16 + g) * 36 + sub * 16 + tg * 4;
                int r1 = r0 + 8 * 36;
                agH[mt] = *(const uint4*)(Ah + r0);
                ahH[mt] = *(const uint4*)(Ah + r1);
                agL[mt] = *(const uint4*)(Al + r0);
                ahL[mt] = *(const uint4*)(Al + r1);
            }
            #pragma unroll
            for (int nt = 0; nt < 4; nt++) {
                int c0 = (wn * 32 + nt * 8 + g) * 36 + sub * 16 + tg * 4;
                bgH[nt] = *(const uint4*)(Bh + c0);
                bgL[nt] = *(const uint4*)(Bl + c0);
            }

            #pragma unroll
            for (int step = 0; step < 2; step++) {
                #pragma unroll
                for (int mt = 0; mt < 2; mt++) {
                    unsigned aH[4], aL[4];
                    if (step == 0) {
                        aH[0] = agH[mt].x; aH[1] = ahH[mt].x; aH[2] = agH[mt].y; aH[3] = ahH[mt].y;
                        aL[0] = agL[mt].x; aL[1] = ahL[mt].x; aL[2] = agL[mt].y; aL[3] = ahL[mt].y;
                    } else {
                        aH[0] = agH[mt].z; aH[1] = ahH[mt].z; aH[2] = agH[mt].w; aH[3] = ahH[mt].w;
                        aL[0] = agL[mt].z; aL[1] = ahL[mt].z; aL[2] = agL[mt].w; aL[3] = ahL[mt].w;
                    }
                    #pragma unroll
                    for (int nt = 0; nt < 4; nt++) {
                        unsigned b0H, b1H, b0L, b1L;
                        if (step == 0) {
                            b0H = bgH[nt].x; b1H = bgH[nt].y;
                            b0L = bgL[nt].x; b1L = bgL[nt].y;
                        } else {
                            b0H = bgH[nt].z; b1H = bgH[nt].w;
                            b0L = bgL[nt].z; b1L = bgL[nt].w;
                        }
                        mma_bf16(acc[mt][nt], aH, b0H, b1H);
                        mma_bf16(acc[mt][nt], aH, b0L, b1L);
                        mma_bf16(acc[mt][nt], aL, b0H, b1H);
                    }
                }
            }
        }
        __syncthreads();
    }

    // ---- Epilogue ----
    const int b = m0 / SS;
    #pragma unroll
    for (int mt = 0; mt < 2; mt++) {
        int m_lo = m0 + wm * 32 + mt * 16 + g;
        #pragma unroll
        for (int nt = 0; nt < 4; nt++) {
            int n = n0 + wn * 32 + nt * 8 + tg * 2;
            int h = n >> 6;
            int d = n & 63;
            int kp = d >> 1;
            int pos = ((kp & 7) << 2) | (kp >> 3);
            #pragma unroll
            for (int rh = 0; rh < 2; rh++) {
                int s = m_lo + 8 * rh - b * SS;
                float vx = acc[mt][nt][2 * rh]     * scale;
                float vy = acc[mt][nt][2 * rh + 1] * scale;
                if (zb == 0) {
                    unsigned ph = packbf(vx, vy);
                    float f0 = __uint_as_float(ph << 16);
                    float f1 = __uint_as_float(ph & 0xFFFF0000u);
                    size_t a = ((size_t)(b * HH + h) * SS + s) * 32 + pos;
                    g_Qh[a] = ph;
                    g_Ql[a] = packbf(vx - f0, vy - f1);
                } else if (zb == 1) {
                    float2 v; v.x = vx; v.y = vy;
                    *(float2*)(g_k + (((size_t)(b * HH + h) * SS + s) * DD + d)) = v;
                    unsigned ph = packbf(vx, vy);
                    float f0 = __uint_as_float(ph << 16);
                    float f1 = __uint_as_float(ph & 0xFFFF0000u);
                    size_t a = ((size_t)(b * HH + h) * UU + WW + s) * 32 + pos;
                    g_Kh[a] = ph;
                    g_Kl[a] = packbf(vx - f0, vy - f1);
                } else {
                    float2 v; v.x = vx; v.y = vy;
                    *(float2*)(g_v + (((size_t)(b * HH + h) * SS + s) * DD + d)) = v;
                }
            }
        }
    }
}

// ---------------------------------------------------------------------------
// Attention (full flash, all-bf16, zero in-loop packing): staging is pure
// cp.async from pre-packed global operands.  QK + PV bf16-split m16n8k16.
// (unchanged from R14 — proven)
// ---------------------------------------------------------------------------
#define AQH_OFF  0
#define AQL_OFF  4608
#define AKH_OFF  9216
#define AKL_OFF  11520
#define AVH_OFF  13824
#define AVL_OFF  16128
#define AB_OFF   18432
#define ATTN_SMEM (18944 * 4)    // 75776 bytes -> 3 blocks/SM

__global__ __launch_bounds__(128, 3) void attn_kernel(
    const float* __restrict__ rel_bias,
    float* __restrict__ out)
{
    extern __shared__ float sm[];
    unsigned* Qph    = (unsigned*)(sm + AQH_OFF);
    unsigned* Qpl    = (unsigned*)(sm + AQL_OFF);
    unsigned* Kph    = (unsigned*)(sm + AKH_OFF);
    unsigned* Kpl    = (unsigned*)(sm + AKL_OFF);
    unsigned* Vth    = (unsigned*)(sm + AVH_OFF);
    unsigned* Vtl    = (unsigned*)(sm + AVL_OFF);
    float*    bias_s = sm + AB_OFF;

    unsigned sb;
    {
        void* p = sm;
        asm("{ .reg .u64 t; cvta.to.shared.u64 t, %1; cvt.u32.u64 %0, t; }"
            : "=r"(sb) : "l"(p));
    }

    const int chunk = blockIdx.x;          // 0..3
    const int h     = blockIdx.y;          // 0..7
    const int bn    = blockIdx.z;          // 0..15
    const int b = bn / NWIN;
    const int n = bn % NWIN;
    const int t = threadIdx.x;
    const int w    = t >> 5;
    const int lane = t & 31;
    const int g    = lane >> 2;
    const int tg   = lane & 3;

    const int q0 = n * WW + chunk * 128;
    const int qb = w * 32;
    const int pbase = q0 + qb;

    // ---- Q stage via cp.async (once) ----
    {
        const unsigned* srcH = g_Qh + ((size_t)(b * HH + h) * SS + q0) * 32;
        const unsigned* srcL = g_Ql + ((size_t)(b * HH + h) * SS + q0) * 32;
        for (int i = t; i < 128 * 8; i += 128) {
            int row = i >> 3, c4 = i & 7;
            unsigned d = sb + (unsigned)(row * 36 + c4 * 4) * 4;
            cp16(d + AQH_OFF * 4, srcH + row * 32 + c4 * 4);
            cp16(d + AQL_OFF * 4, srcL + row * 32 + c4 * 4);
        }
    }

    // Per-head bias table (pre-shifted by -SMAX)
    for (int i = t; i < WW; i += 128) {
        int bucket;
        if (i < 16) {
            bucket = i;
        } else {
            float nf = (float)i;
            float tv = logf(nf * 0.0625f) / 2.0794415416798357f * 16.0f;
            int vi = 16 + (int)tv;
            bucket = (vi < NBUCKETS - 1) ? vi : (NBUCKETS - 1);
        }
        bias_s[i] = rel_bias[h * NBUCKETS + bucket] - SMAX;
    }

    float accPV[2][8][4];
    #pragma unroll
    for (int m = 0; m < 2; m++)
        #pragma unroll
        for (int v = 0; v < 8; v++)
            #pragma unroll
            for (int r = 0; r < 4; r++) accPV[m][v][r] = 0.0f;
    float lrun[2][2] = {{0.0f, 0.0f}, {0.0f, 0.0f}};

    const int kt0 = q0 - WW;

    for (int tile = 0; tile < 10; tile++) {
        const int kt = kt0 + tile * 64;
        const int ku = kt + WW;                  // unified row base (>= 0)
        __syncthreads();

        // ---- K stage: 64 rows x 8 chunks x hi/lo ----
        {
            const unsigned* srcH = g_Kh + ((size_t)(b * HH + h) * UU + ku) * 32;
            const unsigned* srcL = g_Kl + ((size_t)(b * HH + h) * UU + ku) * 32;
            for (int i = t; i < 64 * 8; i += 128) {
                int row = i >> 3, c4 = i & 7;
                unsigned d = sb + (unsigned)(row * 36 + c4 * 4) * 4;
                cp16(d + AKH_OFF * 4, srcH + row * 32 + c4 * 4);
                cp16(d + AKL_OFF * 4, srcL + row * 32 + c4 * 4);
            }
        }
        // ---- V stage: 64 d-rows x 8 chunks x hi/lo (32 pair-words per row) ----
        {
            const unsigned* srcH = g_Vh + (size_t)(b * HH + h) * DD * (UU / 2) + (ku >> 1);
            const unsigned* srcL = g_Vl + (size_t)(b * HH + h) * DD * (UU / 2) + (ku >> 1);
            for (int i = t; i < 64 * 8; i += 128) {
                int row = i >> 3, c4 = i & 7;
                unsigned d = sb + (unsigned)(row * 36 + c4 * 4) * 4;
                cp16(d + AVH_OFF * 4, srcH + (size_t)row * (UU / 2) + c4 * 4);
                cp16(d + AVL_OFF * 4, srcL + (size_t)row * (UU / 2) + c4 * 4);
            }
        }
        cp_commit();
        cp_wait0();
        __syncthreads();

        #pragma unroll
        for (int half = 0; half < 2; half++) {
            const int ks0 = kt + half * 32;
            int jloW = pbase - (WW - 1) - ks0; if (jloW < 0) jloW = 0;
            int jhiW = pbase + 31 - ks0;       if (jhiW > 31) jhiW = 31;
            if (jloW > jhiW) continue;         // warp-uniform skip

            float c[2][4][4];
            #pragma unroll
            for (int m = 0; m < 2; m++)
                #pragma unroll
                for (int nt = 0; nt < 4; nt++)
                    #pragma unroll
                    for (int r = 0; r < 4; r++) c[m][nt][r] = 0.0f;

            #pragma unroll
            for (int m = 0; m < 2; m++) {
                int rg = (qb + m * 16 + g) * 36 + (tg << 2);
                uint4 A0h  = *(const uint4*)&Qph[rg];
                uint4 A1h  = *(const uint4*)&Qph[rg + 16];
                uint4 A0h8 = *(const uint4*)&Qph[rg + 288];
                uint4 A1h8 = *(const uint4*)&Qph[rg + 304];
                uint4 A0l  = *(const uint4*)&Qpl[rg];
                uint4 A1l  = *(const uint4*)&Qpl[rg + 16];
                uint4 A0l8 = *(const uint4*)&Qpl[rg + 288];
                uint4 A1l8 = *(const uint4*)&Qpl[rg + 304];
                unsigned aH[4][4] = {
                    {A0h.x, A0h8.x, A1h.x, A1h8.x},
                    {A0h.y, A0h8.y, A1h.y, A1h8.y},
                    {A0h.z, A0h8.z, A1h.z, A1h8.z},
                    {A0h.w, A0h8.w, A1h.w, A1h8.w}};
                unsigned aL[4][4] = {
                    {A0l.x, A0l8.x, A1l.x, A1l8.x},
                    {A0l.y, A0l8.y, A1l.y, A1l8.y},
                    {A0l.z, A0l8.z, A1l.z, A1l8.z},
                    {A0l.w, A0l8.w, A1l.w, A1l8.w}};
                #pragma unroll
                for (int nt = 0; nt < 4; nt++) {
                    int kr = (half * 32 + nt * 8 + g) * 36 + (tg << 2);
                    uint4 B0h = *(const uint4*)&Kph[kr];
                    uint4 B1h = *(const uint4*)&Kph[kr + 16];
                    uint4 B0l = *(const uint4*)&Kpl[kr];
                    uint4 B1l = *(const uint4*)&Kpl[kr + 16];
                    unsigned b0h[4] = {B0h.x, B0h.y, B0h.z, B0h.w};
                    unsigned b1h[4] = {B1h.x, B1h.y, B1h.z, B1h.w};
                    unsigned b0l[4] = {B0l.x, B0l.y, B0l.z, B0l.w};
                    unsigned b1l[4] = {B1l.x, B1l.y, B1l.z, B1l.w};
                    #pragma unroll
                    for (int ks = 0; ks < 4; ks++) {
                        mma_bf16(c[m][nt], aH[ks], b0h[ks], b1h[ks]);
                        mma_bf16(c[m][nt], aH[ks], b0l[ks], b1l[ks]);
                        mma_bf16(c[m][nt], aL[ks], b0h[ks], b1h[ks]);
                    }
                }
            }

            // ---- softmax in registers ----
            #pragma unroll
            for (int m = 0; m < 2; m++) {
                #pragma unroll
                for (int nt = 0; nt < 4; nt++) {
                    int relb = (pbase + m * 16 + g) - (ks0 + nt * 8 + 2 * tg);
                    int r0 = relb, r1 = relb - 1, r2 = relb + 8, r3 = relb + 7;
                    float s0 = ((unsigned)r0 < (unsigned)WW) ? c[m][nt][0] + bias_s[r0 & (WW-1)] : NEGINF;
                    float s1 = ((unsigned)r1 < (unsigned)WW) ? c[m][nt][1] + bias_s[r1 & (WW-1)] : NEGINF;
                    float s2 = ((unsigned)r2 < (unsigned)WW) ? c[m][nt][2] + bias_s[r2 & (WW-1)] : NEGINF;
                    float s3 = ((unsigned)r3 < (unsigned)WW) ? c[m][nt][3] + bias_s[r3 & (WW-1)] : NEGINF;
                    float p0 = __expf(s0), p1 = __expf(s1);
                    float p2 = __expf(s2), p3 = __expf(s3);
                    lrun[m][0] += p0 + p1;
                    lrun[m][1] += p2 + p3;
                    c[m][nt][0] = p0; c[m][nt][1] = p1;
                    c[m][nt][2] = p2; c[m][nt][3] = p3;
                }
            }

            // ---- pack P into bf16 hi/lo A-fragments ----
            unsigned aPh[2][2][4], aPl[2][2][4];
            #pragma unroll
            for (int m = 0; m < 2; m++) {
                #pragma unroll
                for (int kk = 0; kk < 2; kk++) {
                    #pragma unroll
                    for (int idx = 0; idx < 4; idx++) {
                        int nt = 2 * kk + (idx >> 1);
                        int rb = (idx & 1) * 2;
                        float x = c[m][nt][rb], y = c[m][nt][rb + 1];
                        unsigned ph = packbf(x, y);
                        float fx = __uint_as_float(ph << 16);
                        float fy = __uint_as_float(ph & 0xFFFF0000u);
                        aPh[m][kk][idx] = ph;
                        aPl[m][kk][idx] = packbf(x - fx, y - fy);
                    }
                }
            }

            // ---- PV mma ----
            #pragma unroll
            for (int kk = 0; kk < 2; kk++) {
                #pragma unroll
                for (int ntv = 0; ntv < 8; ntv++) {
                    int vb = (ntv * 8 + g) * 36 + half * 16 + kk * 8 + tg;
                    unsigned bh0 = Vth[vb], bh1 = Vth[vb + 4];
                    unsigned bl0 = Vtl[vb], bl1 = Vtl[vb + 4];
                    #pragma unroll
                    for (int m = 0; m < 2; m++) {
                        mma_bf16(accPV[m][ntv], aPh[m][kk], bh0, bh1);
                        mma_bf16(accPV[m][ntv], aPh[m][kk], bl0, bl1);
                        mma_bf16(accPV[m][ntv], aPl[m][kk], bh0, bh1);
                    }
                }
            }
        }
    }

    // ---- finish: quad-reduce lrun, scale, store ----
    float linv[2][2];
    #pragma unroll
    for (int m = 0; m < 2; m++) {
        #pragma unroll
        for (int rh = 0; rh < 2; rh++) {
            float l = lrun[m][rh];
            l += __shfl_xor_sync(0xffffffffu, l, 1);
            l += __shfl_xor_sync(0xffffffffu, l, 2);
            linv[m][rh] = 1.0f / l;
        }
    }

    #pragma unroll
    for (int m = 0; m < 2; m++) {
        #pragma unroll
        for (int rh = 0; rh < 2; rh++) {
            int qrow = q0 + qb + m * 16 + g + 8 * rh;
            float* op = out + (((size_t)(b * SS + qrow) * HH + h) * DD);
            float li = linv[m][rh];
            #pragma unroll
            for (int ntv = 0; ntv < 8; ntv++) {
                float2 v;
                v.x = accPV[m][ntv][2 * rh]     * li;
                v.y = accPV[m][ntv][2 * rh + 1] * li;
                *(float2*)(op + ntv * 8 + 2 * tg) = v;
            }
        }
    }
}

// ---------------------------------------------------------------------------
// Tail: next_k / next_v = last window of k / v, layout (B, W, H, D)
// ---------------------------------------------------------------------------
__global__ __launch_bounds__(256) void tail_kernel(float* __restrict__ out)
{
    const size_t OFF_K = (size_t)BB * SS * HH * DD;             // 4194304
    const size_t OFF_V = OFF_K + (size_t)BB * WW * HH * DD;     // 4718592
    int i = blockIdx.x * 256 + threadIdx.x;                     // < 524288
    int b = i / (WW * HH * DD);
    int r = i % (WW * HH * DD);
    int w = r / (HH * DD);
    int r2 = r % (HH * DD);
    int h = r2 / DD;
    int d = r2 % DD;
    size_t src = (((size_t)(b * HH + h) * SS + (SS - WW + w)) * DD + d);
    out[OFF_K + i] = g_k[src];
    out[OFF_V + i] = g_v[src];
}

// ---------------------------------------------------------------------------
extern "C" void kernel_launch(void* const* d_in, const int* in_sizes, int n_in,
                              void* d_out, int out_size)
{
    const float* xs       = (const float*)d_in[0];
    const float* prev_k   = (const float*)d_in[1];
    const float* prev_v   = (const float*)d_in[2];
    const float* w_q      = (const float*)d_in[3];
    const float* w_k      = (const float*)d_in[4];
    const float* w_v      = (const float*)d_in[5];
    const float* rel_bias = (const float*)d_in[6];
    float* out = (float*)d_out;

    static bool attr_set = false;
    if (!attr_set) {
        cudaFuncSetAttribute(proj_kernel,
                             cudaFuncAttributeMaxDynamicSharedMemorySize, PROJ_SMEM);
        cudaFuncSetAttribute(attn_kernel,
                             cudaFuncAttributeMaxDynamicSharedMemorySize, ATTN_SMEM);
        attr_set = true;
    }

    split_xs_kernel<<<BB*SS*EE/2/256, 256>>>(xs);
    split_w_kernel<<<dim3(16, 16, 3), 256>>>(w_q, w_k, w_v);
    pk_pack_kernel<<<BB*WW*HH*32/256, 256>>>(prev_k);

    dim3 pg(64, 4, 3);                 // M/128, N/128, {q,k,v}
    proj_kernel<<<pg, 512, PROJ_SMEM>>>();

    vt_pack_kernel<<<dim3(UU/128, BB*HH), 256>>>(prev_v);

    dim3 ag(4, HH, BB * NWIN);         // 128-query chunks, heads, batch*windows
    attn_kernel<<<ag, 128, ATTN_SMEM>>>(rel_bias, out);

    tail_kernel<<<2048, 256>>>(out);
}

// round 17
// speedup vs baseline: 1.1687x; 1.1687x over previous
#include <cuda_runtime.h>
#include <math.h>

// Problem constants
#define BB 2
#define SS 4096
#define EE 512
#define HH 8
#define DD 64
#define WW 512
#define NWIN 8            // SS / WW
#define NBUCKETS 32
#define UU (WW + SS)      // unified key axis: [0,W) prev, [W, W+S) current

#define NEGINF (-INFINITY)
#define SMAX 16.0f        // static softmax shift (scores are O(+-10))

#define OFFK ((size_t)BB * SS * HH * DD)            // 4194304
#define OFFV (OFFK + (size_t)BB * WW * HH * DD)     // 4718592

// Scratch fp32 (v needed by vt_pack)
__device__ float g_v[BB*HH*SS*DD];

// bf16x2-packed hi/lo splits for the proj GEMM, pair-permuted per 16-pair chunk
__device__ __align__(16) unsigned g_xp_hi[BB*SS*EE/2];     // [m][256]
__device__ __align__(16) unsigned g_xp_lo[BB*SS*EE/2];
__device__ __align__(16) unsigned g_wp_hi[3*EE*HH*DD/2];   // [zb][n][256] (transposed)
__device__ __align__(16) unsigned g_wp_lo[3*EE*HH*DD/2];

// Packed attention operands (bf16x2 hi/lo)
__device__ __align__(16) unsigned g_Qh[BB*HH*SS*32];       // [b][h][s][pos]
__device__ __align__(16) unsigned g_Ql[BB*HH*SS*32];
__device__ __align__(16) unsigned g_Kh[BB*HH*UU*32];       // [b][h][u][pos]
__device__ __align__(16) unsigned g_Kl[BB*HH*UU*32];
__device__ __align__(16) unsigned g_Vh[BB*HH*DD*(UU/2)];   // [b][h][d][sp]
__device__ __align__(16) unsigned g_Vl[BB*HH*DD*(UU/2)];

// ---------------------------------------------------------------------------
// helpers
// ---------------------------------------------------------------------------
__device__ __forceinline__ void mma_bf16(float c[4], const unsigned a[4],
                                         unsigned b0, unsigned b1) {
    asm volatile(
        "mma.sync.aligned.m16n8k16.row.col.f32.bf16.bf16.f32 "
        "{%0,%1,%2,%3}, {%4,%5,%6,%7}, {%8,%9}, {%0,%1,%2,%3};"
        : "+f"(c[0]), "+f"(c[1]), "+f"(c[2]), "+f"(c[3])
        : "r"(a[0]), "r"(a[1]), "r"(a[2]), "r"(a[3]), "r"(b0), "r"(b1));
}

// pack two f32 into bf16x2: lower half = first arg, upper half = second arg
__device__ __forceinline__ unsigned packbf(float lo, float hi) {
    unsigned r;
    asm("cvt.rn.bf16x2.f32 %0, %1, %2;" : "=r"(r) : "f"(hi), "f"(lo));
    return r;
}

__device__ __forceinline__ void cp16(unsigned s, const void* g) {
    asm volatile("cp.async.cg.shared.global [%0], [%1], 16;" :: "r"(s), "l"(g));
}
__device__ __forceinline__ void cp_commit() { asm volatile("cp.async.commit_group;"); }
__device__ __forceinline__ void cp_wait1()  { asm volatile("cp.async.wait_group 1;"); }
__device__ __forceinline__ void cp_wait0()  { asm volatile("cp.async.wait_group 0;"); }

// ---------------------------------------------------------------------------
// Pre-split xs (proj A operand): packed bf16x2 hi/lo, pair-permuted
// ---------------------------------------------------------------------------
__global__ __launch_bounds__(256) void split_xs_kernel(const float* __restrict__ xs)
{
    int id = blockIdx.x * 256 + threadIdx.x;       // < B*S*E/2 = 2M
    int m  = id >> 8;
    int pk = id & 255;
    float x0 = xs[m * 512 + 2 * pk];
    float x1 = xs[m * 512 + 2 * pk + 1];
    unsigned ph = packbf(x0, x1);
    float f0 = __uint_as_float(ph << 16);
    float f1 = __uint_as_float(ph & 0xFFFF0000u);
    unsigned pl = packbf(x0 - f0, x1 - f1);
    int j  = pk & 15, ch = pk >> 4;
    int pos = (m << 8) | (ch << 4) | ((j & 3) << 2) | (j >> 2);
    g_xp_hi[pos] = ph;
    g_xp_lo[pos] = pl;
}

// ---------------------------------------------------------------------------
// Pre-split weights: transpose [e][n] -> [n][e], pack bf16x2 hi/lo, permute.
// ---------------------------------------------------------------------------
__global__ __launch_bounds__(256) void split_w_kernel(
    const float* __restrict__ wq,
    const float* __restrict__ wk,
    const float* __restrict__ wv)
{
    const int zb = blockIdx.z;
    const float* w = (zb == 0) ? wq : (zb == 1) ? wk : wv;

    __shared__ float t[32][33];

    const int e0 = blockIdx.x * 32;
    const int n0 = blockIdx.y * 32;
    const int lx = threadIdx.x & 31;
    const int ly = threadIdx.x >> 5;

    #pragma unroll
    for (int r = 0; r < 4; r++) {
        int e = e0 + ly + r * 8;
        t[lx][ly + r * 8] = w[e * 512 + n0 + lx];
    }
    __syncthreads();

    for (int i = threadIdx.x; i < 32 * 16; i += 256) {
        int n_local = i >> 4;
        int j = i & 15;
        float x0 = t[n_local][2 * j];
        float x1 = t[n_local][2 * j + 1];
        unsigned ph = packbf(x0, x1);
        float f0 = __uint_as_float(ph << 16);
        float f1 = __uint_as_float(ph & 0xFFFF0000u);
        unsigned pl = packbf(x0 - f0, x1 - f1);
        int pos = (zb * 512 + n0 + n_local) * 256 + (blockIdx.x << 4)
                  + ((j & 3) << 2) + (j >> 2);
        g_wp_hi[pos] = ph;
        g_wp_lo[pos] = pl;
    }
}

// ---------------------------------------------------------------------------
// Pack prev_k into unified K rows [0, W)
// ---------------------------------------------------------------------------
__global__ __launch_bounds__(256) void pk_pack_kernel(const float* __restrict__ prev_k)
{
    int id = blockIdx.x * 256 + threadIdx.x;       // < B*W*H*32 = 262144
    int dp = id & 31;
    int h  = (id >> 5) & 7;
    int w  = (id >> 8) & 511;
    int b  = id >> 17;
    const float* src = prev_k + (((size_t)(b * WW + w) * HH + h) * DD) + 2 * dp;
    float x0 = src[0], x1 = src[1];
    unsigned ph = packbf(x0, x1);
    float f0 = __uint_as_float(ph << 16);
    float f1 = __uint_as_float(ph & 0xFFFF0000u);
    int pos = ((dp & 7) << 2) | (dp >> 3);
    size_t dst = ((size_t)(b * HH + h) * UU + w) * 32 + pos;
    g_Kh[dst] = ph;
    g_Kl[dst] = packbf(x0 - f0, x1 - f1);
}

// ---------------------------------------------------------------------------
// V transpose + pack: g_Vh/g_Vl [b][h][d][sp], sp = unified s-pair.
// grid (36, B*H), block 256.  Chunk = 128 unified rows.
// ---------------------------------------------------------------------------
__global__ __launch_bounds__(256) void vt_pack_kernel(const float* __restrict__ prev_v)
{
    __shared__ float tile[128][65];
    const int c  = blockIdx.x;                     // 0..35
    const int bh = blockIdx.y;                     // 0..15
    const int b = bh >> 3, h = bh & 7;
    const int t = threadIdx.x;

    for (int i = t; i < 128 * 64; i += 256) {
        int row = i >> 6, d = i & 63;
        int u = c * 128 + row;
        float val;
        if (u < WW)
            val = prev_v[(((size_t)(b * WW + u) * HH + h) * DD) + d];
        else
            val = g_v[(((size_t)(b * HH + h) * SS + (u - WW)) * DD) + d];
        tile[row][d] = val;
    }
    __syncthreads();

    for (int i = t; i < 64 * 64; i += 256) {
        int d = i >> 6, spl = i & 63;
        float x0 = tile[2 * spl][d];
        float x1 = tile[2 * spl + 1][d];
        unsigned ph = packbf(x0, x1);
        float f0 = __uint_as_float(ph << 16);
        float f1 = __uint_as_float(ph & 0xFFFF0000u);
        size_t dst = ((size_t)(b * HH + h) * DD + d) * (UU / 2) + c * 64 + spl;
        g_Vh[dst] = ph;
        g_Vl[dst] = packbf(x0 - f0, x1 - f1);
    }
}

// ---------------------------------------------------------------------------
// Projection via bf16-split (3-term) m16n8k16 GEMM.
// 512 threads, 16 warps (4x4 grid of 32x32 warp tiles).
// R15 layout (stride-16 rows, conflict-free) but chunks processed in PAIRS:
// 4 buffers x 8192 words; one barrier pair per 2 chunks (16 barriers total).
// Epilogue: zb=0 -> packed Q; zb=1 -> packed K + next_k to out;
//           zb=2 -> fp32 V + next_v to out.
// ---------------------------------------------------------------------------
#define PROJ_SMEM (4 * 8192 * 4)   // 131072 bytes

__global__ __launch_bounds__(512, 1) void proj_kernel(float* __restrict__ out)
{
    extern __shared__ unsigned smem[];   // [4][4][2048]

    const int zb = blockIdx.z;
    const float scale = (zb == 0) ? 0.125f : 1.0f;

    const int m0 = blockIdx.x * 128;
    const int n0 = blockIdx.y * 128;
    const int tid  = threadIdx.x;
    const int wid  = tid >> 5;
    const int lane = tid & 31;
    const int g    = lane >> 2;
    const int tg   = lane & 3;
    const int wm   = wid >> 2;      // 0..3 (32 rows each)
    const int wn   = wid & 3;       // 0..3 (32 cols each)

    unsigned smem_u32;
    {
        void* p = smem;
        asm("{ .reg .u64 t; cvta.to.shared.u64 t, %1; cvt.u32.u64 %0, t; }"
            : "=r"(smem_u32) : "l"(p));
    }

    // staging: one float4 slot per array per thread (R15 layout, stride 16)
    const int srow = tid >> 2, sc4 = tid & 3;

    float acc[2][4][4];
    #pragma unroll
    for (int mt = 0; mt < 2; mt++)
        #pragma unroll
        for (int nt = 0; nt < 4; nt++)
            #pragma unroll
            for (int r = 0; r < 4; r++) acc[mt][nt][r] = 0.0f;

    auto stage = [&](int buf, int ch) {
        unsigned base = smem_u32 + (unsigned)buf * 8192 * 4;
        unsigned d = base + (unsigned)(srow * 16 + sc4 * 4) * 4;
        const unsigned* aH = g_xp_hi + ((m0 + srow) * 256 + ch * 16 + sc4 * 4);
        const unsigned* aL = g_xp_lo + ((m0 + srow) * 256 + ch * 16 + sc4 * 4);
        cp16(d,            aH);
        cp16(d + 2048 * 4, aL);
        const unsigned* bH = g_wp_hi + ((size_t)(zb * 512 + n0 + srow) * 256 + ch * 16 + sc4 * 4);
        const unsigned* bL = g_wp_lo + ((size_t)(zb * 512 + n0 + srow) * 256 + ch * 16 + sc4 * 4);
        cp16(d + 4096 * 4, bH);
        cp16(d + 6144 * 4, bL);
    };

    // prologue: stage pair 0 (chunks 0,1) as one commit group
    stage(0, 0);
    stage(1, 1);
    cp_commit();

    for (int p = 0; p < 8; p++) {
        if (p < 7) {
            int q1 = (p + 1) & 1;
            stage(2 * q1,     2 * p + 2);
            stage(2 * q1 + 1, 2 * p + 3);
            cp_commit();
            cp_wait1();
        } else {
            cp_wait0();
        }
        __syncthreads();

        const int q = p & 1;
        #pragma unroll
        for (int sub = 0; sub < 2; sub++) {
            const unsigned* Ah = smem + (2 * q + sub) * 8192;
            const unsigned* Al = Ah + 2048;
            const unsigned* Bh = Ah + 4096;
            const unsigned* Bl = Ah + 6144;

            uint4 agH[2], ahH[2], agL[2], ahL[2], bgH[4], bgL[4];
            #pragma unroll
            for (int mt = 0; mt < 2; mt++) {
                int r0 = (wm * 32 + mt * 16 + g) * 16 + tg * 4;
                int r1 = r0 + 8 * 16;
                agH[mt] = *(const uint4*)(Ah + r0);
                ahH[mt] = *(const uint4*)(Ah + r1);
                agL[mt] = *(const uint4*)(Al + r0);
                ahL[mt] = *(const uint4*)(Al + r1);
            }
            #pragma unroll
            for (int nt = 0; nt < 4; nt++) {
                int c0 = (wn * 32 + nt * 8 + g) * 16 + tg * 4;
                bgH[nt] = *(const uint4*)(Bh + c0);
                bgL[nt] = *(const uint4*)(Bl + c0);
            }

            #pragma unroll
            for (int step = 0; step < 2; step++) {
                #pragma unroll
                for (int mt = 0; mt < 2; mt++) {
                    unsigned aH[4], aL[4];
                    if (step == 0) {
                        aH[0] = agH[mt].x; aH[1] = ahH[mt].x; aH[2] = agH[mt].y; aH[3] = ahH[mt].y;
                        aL[0] = agL[mt].x; aL[1] = ahL[mt].x; aL[2] = agL[mt].y; aL[3] = ahL[mt].y;
                    } else {
                        aH[0] = agH[mt].z; aH[1] = ahH[mt].z; aH[2] = agH[mt].w; aH[3] = ahH[mt].w;
                        aL[0] = agL[mt].z; aL[1] = ahL[mt].z; aL[2] = agL[mt].w; aL[3] = ahL[mt].w;
                    }
                    #pragma unroll
                    for (int nt = 0; nt < 4; nt++) {
                        unsigned b0H, b1H, b0L, b1L;
                        if (step == 0) {
                            b0H = bgH[nt].x; b1H = bgH[nt].y;
                            b0L = bgL[nt].x; b1L = bgL[nt].y;
                        } else {
                            b0H = bgH[nt].z; b1H = bgH[nt].w;
                            b0L = bgL[nt].z; b1L = bgL[nt].w;
                        }
                        mma_bf16(acc[mt][nt], aH, b0H, b1H);
                        mma_bf16(acc[mt][nt], aH, b0L, b1L);
                        mma_bf16(acc[mt][nt], aL, b0H, b1H);
                    }
                }
            }
        }
        __syncthreads();
    }

    // ---- Epilogue ----
    const int b = m0 / SS;
    #pragma unroll
    for (int mt = 0; mt < 2; mt++) {
        int m_lo = m0 + wm * 32 + mt * 16 + g;
        #pragma unroll
        for (int nt = 0; nt < 4; nt++) {
            int n = n0 + wn * 32 + nt * 8 + tg * 2;
            int h = n >> 6;
            int d = n & 63;
            int kp = d >> 1;
            int pos = ((kp & 7) << 2) | (kp >> 3);
            #pragma unroll
            for (int rh = 0; rh < 2; rh++) {
                int s = m_lo + 8 * rh - b * SS;
                float vx = acc[mt][nt][2 * rh]     * scale;
                float vy = acc[mt][nt][2 * rh + 1] * scale;
                if (zb == 0) {
                    unsigned ph = packbf(vx, vy);
                    float f0 = __uint_as_float(ph << 16);
                    float f1 = __uint_as_float(ph & 0xFFFF0000u);
                    size_t a = ((size_t)(b * HH + h) * SS + s) * 32 + pos;
                    g_Qh[a] = ph;
                    g_Ql[a] = packbf(vx - f0, vy - f1);
                } else if (zb == 1) {
                    unsigned ph = packbf(vx, vy);
                    float f0 = __uint_as_float(ph << 16);
                    float f1 = __uint_as_float(ph & 0xFFFF0000u);
                    size_t a = ((size_t)(b * HH + h) * UU + WW + s) * 32 + pos;
                    g_Kh[a] = ph;
                    g_Kl[a] = packbf(vx - f0, vy - f1);
                    if (s >= SS - WW) {
                        int w = s - (SS - WW);
                        float2 v; v.x = vx; v.y = vy;
                        *(float2*)(out + OFFK + (((size_t)(b * WW + w) * HH + h) * DD + d)) = v;
                    }
                } else {
                    float2 v; v.x = vx; v.y = vy;
                    *(float2*)(g_v + (((size_t)(b * HH + h) * SS + s) * DD + d)) = v;
                    if (s >= SS - WW) {
                        int w = s - (SS - WW);
                        *(float2*)(out + OFFV + (((size_t)(b * WW + w) * HH + h) * DD + d)) = v;
                    }
                }
            }
        }
    }
}

// ---------------------------------------------------------------------------
// Attention (full flash, all-bf16, zero in-loop packing): staging is pure
// cp.async from pre-packed global operands.  QK + PV bf16-split m16n8k16.
// (unchanged from R14 — proven)
// ---------------------------------------------------------------------------
#define AQH_OFF  0
#define AQL_OFF  4608
#define AKH_OFF  9216
#define AKL_OFF  11520
#define AVH_OFF  13824
#define AVL_OFF  16128
#define AB_OFF   18432
#define ATTN_SMEM (18944 * 4)    // 75776 bytes -> 3 blocks/SM

__global__ __launch_bounds__(128, 3) void attn_kernel(
    const float* __restrict__ rel_bias,
    float* __restrict__ out)
{
    extern __shared__ float sm[];
    unsigned* Qph    = (unsigned*)(sm + AQH_OFF);
    unsigned* Qpl    = (unsigned*)(sm + AQL_OFF);
    unsigned* Kph    = (unsigned*)(sm + AKH_OFF);
    unsigned* Kpl    = (unsigned*)(sm + AKL_OFF);
    unsigned* Vth    = (unsigned*)(sm + AVH_OFF);
    unsigned* Vtl    = (unsigned*)(sm + AVL_OFF);
    float*    bias_s = sm + AB_OFF;

    unsigned sb;
    {
        void* p = sm;
        asm("{ .reg .u64 t; cvta.to.shared.u64 t, %1; cvt.u32.u64 %0, t; }"
            : "=r"(sb) : "l"(p));
    }

    const int chunk = blockIdx.x;          // 0..3
    const int h     = blockIdx.y;          // 0..7
    const int bn    = blockIdx.z;          // 0..15
    const int b = bn / NWIN;
    const int n = bn % NWIN;
    const int t = threadIdx.x;
    const int w    = t >> 5;
    const int lane = t & 31;
    const int g    = lane >> 2;
    const int tg   = lane & 3;

    const int q0 = n * WW + chunk * 128;
    const int qb = w * 32;
    const int pbase = q0 + qb;

    // ---- Q stage via cp.async (once) ----
    {
        const unsigned* srcH = g_Qh + ((size_t)(b * HH + h) * SS + q0) * 32;
        const unsigned* srcL = g_Ql + ((size_t)(b * HH + h) * SS + q0) * 32;
        for (int i = t; i < 128 * 8; i += 128) {
            int row = i >> 3, c4 = i & 7;
            unsigned d = sb + (unsigned)(row * 36 + c4 * 4) * 4;
            cp16(d + AQH_OFF * 4, srcH + row * 32 + c4 * 4);
            cp16(d + AQL_OFF * 4, srcL + row * 32 + c4 * 4);
        }
    }

    // Per-head bias table (pre-shifted by -SMAX)
    for (int i = t; i < WW; i += 128) {
        int bucket;
        if (i < 16) {
            bucket = i;
        } else {
            float nf = (float)i;
            float tv = logf(nf * 0.0625f) / 2.0794415416798357f * 16.0f;
            int vi = 16 + (int)tv;
            bucket = (vi < NBUCKETS - 1) ? vi : (NBUCKETS - 1);
        }
        bias_s[i] = rel_bias[h * NBUCKETS + bucket] - SMAX;
    }

    float accPV[2][8][4];
    #pragma unroll
    for (int m = 0; m < 2; m++)
        #pragma unroll
        for (int v = 0; v < 8; v++)
            #pragma unroll
            for (int r = 0; r < 4; r++) accPV[m][v][r] = 0.0f;
    float lrun[2][2] = {{0.0f, 0.0f}, {0.0f, 0.0f}};

    const int kt0 = q0 - WW;

    for (int tile = 0; tile < 10; tile++) {
        const int kt = kt0 + tile * 64;
        const int ku = kt + WW;                  // unified row base (>= 0)
        __syncthreads();

        // ---- K stage: 64 rows x 8 chunks x hi/lo ----
        {
            const unsigned* srcH = g_Kh + ((size_t)(b * HH + h) * UU + ku) * 32;
            const unsigned* srcL = g_Kl + ((size_t)(b * HH + h) * UU + ku) * 32;
            for (int i = t; i < 64 * 8; i += 128) {
                int row = i >> 3, c4 = i & 7;
                unsigned d = sb + (unsigned)(row * 36 + c4 * 4) * 4;
                cp16(d + AKH_OFF * 4, srcH + row * 32 + c4 * 4);
                cp16(d + AKL_OFF * 4, srcL + row * 32 + c4 * 4);
            }
        }
        // ---- V stage: 64 d-rows x 8 chunks x hi/lo (32 pair-words per row) ----
        {
            const unsigned* srcH = g_Vh + (size_t)(b * HH + h) * DD * (UU / 2) + (ku >> 1);
            const unsigned* srcL = g_Vl + (size_t)(b * HH + h) * DD * (UU / 2) + (ku >> 1);
            for (int i = t; i < 64 * 8; i += 128) {
                int row = i >> 3, c4 = i & 7;
                unsigned d = sb + (unsigned)(row * 36 + c4 * 4) * 4;
                cp16(d + AVH_OFF * 4, srcH + (size_t)row * (UU / 2) + c4 * 4);
                cp16(d + AVL_OFF * 4, srcL + (size_t)row * (UU / 2) + c4 * 4);
            }
        }
        cp_commit();
        cp_wait0();
        __syncthreads();

        #pragma unroll
        for (int half = 0; half < 2; half++) {
            const int ks0 = kt + half * 32;
            int jloW = pbase - (WW - 1) - ks0; if (jloW < 0) jloW = 0;
            int jhiW = pbase + 31 - ks0;       if (jhiW > 31) jhiW = 31;
            if (jloW > jhiW) continue;         // warp-uniform skip

            float c[2][4][4];
            #pragma unroll
            for (int m = 0; m < 2; m++)
                #pragma unroll
                for (int nt = 0; nt < 4; nt++)
                    #pragma unroll
                    for (int r = 0; r < 4; r++) c[m][nt][r] = 0.0f;

            #pragma unroll
            for (int m = 0; m < 2; m++) {
                int rg = (qb + m * 16 + g) * 36 + (tg << 2);
                uint4 A0h  = *(const uint4*)&Qph[rg];
                uint4 A1h  = *(const uint4*)&Qph[rg + 16];
                uint4 A0h8 = *(const uint4*)&Qph[rg + 288];
                uint4 A1h8 = *(const uint4*)&Qph[rg + 304];
                uint4 A0l  = *(const uint4*)&Qpl[rg];
                uint4 A1l  = *(const uint4*)&Qpl[rg + 16];
                uint4 A0l8 = *(const uint4*)&Qpl[rg + 288];
                uint4 A1l8 = *(const uint4*)&Qpl[rg + 304];
                unsigned aH[4][4] = {
                    {A0h.x, A0h8.x, A1h.x, A1h8.x},
                    {A0h.y, A0h8.y, A1h.y, A1h8.y},
                    {A0h.z, A0h8.z, A1h.z, A1h8.z},
                    {A0h.w, A0h8.w, A1h.w, A1h8.w}};
                unsigned aL[4][4] = {
                    {A0l.x, A0l8.x, A1l.x, A1l8.x},
                    {A0l.y, A0l8.y, A1l.y, A1l8.y},
                    {A0l.z, A0l8.z, A1l.z, A1l8.z},
                    {A0l.w, A0l8.w, A1l.w, A1l8.w}};
                #pragma unroll
                for (int nt = 0; nt < 4; nt++) {
                    int kr = (half * 32 + nt * 8 + g) * 36 + (tg << 2);
                    uint4 B0h = *(const uint4*)&Kph[kr];
                    uint4 B1h = *(const uint4*)&Kph[kr + 16];
                    uint4 B0l = *(const uint4*)&Kpl[kr];
                    uint4 B1l = *(const uint4*)&Kpl[kr + 16];
                    unsigned b0h[4] = {B0h.x, B0h.y, B0h.z, B0h.w};
                    unsigned b1h[4] = {B1h.x, B1h.y, B1h.z, B1h.w};
                    unsigned b0l[4] = {B0l.x, B0l.y, B0l.z, B0l.w};
                    unsigned b1l[4] = {B1l.x, B1l.y, B1l.z, B1l.w};
                    #pragma unroll
                    for (int ks = 0; ks < 4; ks++) {
                        mma_bf16(c[m][nt], aH[ks], b0h[ks], b1h[ks]);
                        mma_bf16(c[m][nt], aH[ks], b0l[ks], b1l[ks]);
                        mma_bf16(c[m][nt], aL[ks], b0h[ks], b1h[ks]);
                    }
                }
            }

            // ---- softmax in registers ----
            #pragma unroll
            for (int m = 0; m < 2; m++) {
                #pragma unroll
                for (int nt = 0; nt < 4; nt++) {
                    int relb = (pbase + m * 16 + g) - (ks0 + nt * 8 + 2 * tg);
                    int r0 = relb, r1 = relb - 1, r2 = relb + 8, r3 = relb + 7;
                    float s0 = ((unsigned)r0 < (unsigned)WW) ? c[m][nt][0] + bias_s[r0 & (WW-1)] : NEGINF;
                    float s1 = ((unsigned)r1 < (unsigned)WW) ? c[m][nt][1] + bias_s[r1 & (WW-1)] : NEGINF;
                    float s2 = ((unsigned)r2 < (unsigned)WW) ? c[m][nt][2] + bias_s[r2 & (WW-1)] : NEGINF;
                    float s3 = ((unsigned)r3 < (unsigned)WW) ? c[m][nt][3] + bias_s[r3 & (WW-1)] : NEGINF;
                    float p0 = __expf(s0), p1 = __expf(s1);
                    float p2 = __expf(s2), p3 = __expf(s3);
                    lrun[m][0] += p0 + p1;
                    lrun[m][1] += p2 + p3;
                    c[m][nt][0] = p0; c[m][nt][1] = p1;
                    c[m][nt][2] = p2; c[m][nt][3] = p3;
                }
            }

            // ---- pack P into bf16 hi/lo A-fragments ----
            unsigned aPh[2][2][4], aPl[2][2][4];
            #pragma unroll
            for (int m = 0; m < 2; m++) {
                #pragma unroll
                for (int kk = 0; kk < 2; kk++) {
                    #pragma unroll
                    for (int idx = 0; idx < 4; idx++) {
                        int nt = 2 * kk + (idx >> 1);
                        int rb = (idx & 1) * 2;
                        float x = c[m][nt][rb], y = c[m][nt][rb + 1];
                        unsigned ph = packbf(x, y);
                        float fx = __uint_as_float(ph << 16);
                        float fy = __uint_as_float(ph & 0xFFFF0000u);
                        aPh[m][kk][idx] = ph;
                        aPl[m][kk][idx] = packbf(x - fx, y - fy);
                    }
                }
            }

            // ---- PV mma ----
            #pragma unroll
            for (int kk = 0; kk < 2; kk++) {
                #pragma unroll
                for (int ntv = 0; ntv < 8; ntv++) {
                    int vb = (ntv * 8 + g) * 36 + half * 16 + kk * 8 + tg;
                    unsigned bh0 = Vth[vb], bh1 = Vth[vb + 4];
                    unsigned bl0 = Vtl[vb], bl1 = Vtl[vb + 4];
                    #pragma unroll
                    for (int m = 0; m < 2; m++) {
                        mma_bf16(accPV[m][ntv], aPh[m][kk], bh0, bh1);
                        mma_bf16(accPV[m][ntv], aPh[m][kk], bl0, bl1);
                        mma_bf16(accPV[m][ntv], aPl[m][kk], bh0, bh1);
                    }
                }
            }
        }
    }

    // ---- finish: quad-reduce lrun, scale, store ----
    float linv[2][2];
    #pragma unroll
    for (int m = 0; m < 2; m++) {
        #pragma unroll
        for (int rh = 0; rh < 2; rh++) {
            float l = lrun[m][rh];
            l += __shfl_xor_sync(0xffffffffu, l, 1);
            l += __shfl_xor_sync(0xffffffffu, l, 2);
            linv[m][rh] = 1.0f / l;
        }
    }

    #pragma unroll
    for (int m = 0; m < 2; m++) {
        #pragma unroll
        for (int rh = 0; rh < 2; rh++) {
            int qrow = q0 + qb + m * 16 + g + 8 * rh;
            float* op = out + (((size_t)(b * SS + qrow) * HH + h) * DD);
            float li = linv[m][rh];
            #pragma unroll
            for (int ntv = 0; ntv < 8; ntv++) {
                float2 v;
                v.x = accPV[m][ntv][2 * rh]     * li;
                v.y = accPV[m][ntv][2 * rh + 1] * li;
                *(float2*)(op + ntv * 8 + 2 * tg) = v;
            }
        }
    }
}

// ---------------------------------------------------------------------------
extern "C" void kernel_launch(void* const* d_in, const int* in_sizes, int n_in,
                              void* d_out, int out_size)
{
    const float* xs       = (const float*)d_in[0];
    const float* prev_k   = (const float*)d_in[1];
    const float* prev_v   = (const float*)d_in[2];
    const float* w_q      = (const float*)d_in[3];
    const float* w_k      = (const float*)d_in[4];
    const float* w_v      = (const float*)d_in[5];
    const float* rel_bias = (const float*)d_in[6];
    float* out = (float*)d_out;

    static bool attr_set = false;
    if (!attr_set) {
        cudaFuncSetAttribute(proj_kernel,
                             cudaFuncAttributeMaxDynamicSharedMemorySize, PROJ_SMEM);
        cudaFuncSetAttribute(attn_kernel,
                             cudaFuncAttributeMaxDynamicSharedMemorySize, ATTN_SMEM);
        attr_set = true;
    }

    split_xs_kernel<<<BB*SS*EE/2/256, 256>>>(xs);
    split_w_kernel<<<dim3(16, 16, 3), 256>>>(w_q, w_k, w_v);
    pk_pack_kernel<<<BB*WW*HH*32/256, 256>>>(prev_k);

    dim3 pg(64, 4, 3);                 // M/128, N/128, {q,k,v}
    proj_kernel<<<pg, 512, PROJ_SMEM>>>(out);

    vt_pack_kernel<<<dim3(UU/128, BB*HH), 256>>>(prev_v);

    dim3 ag(4, HH, BB * NWIN);         // 128-query chunks, heads, batch*windows
    attn_kernel<<<ag, 128, ATTN_SMEM>>>(rel_bias, out);
}